// round 12
// baseline (speedup 1.0000x reference)
#include <cuda_runtime.h>
#include <cuda_bf16.h>
#include <math.h>
#include <stdint.h>

// Problem constants
#define D    80
#define E    8
#define HID  320
#define NL   4
#define TBK  256           // tokens per ffn tile
#define NCK  5             // HID chunks of 64
#define MAXT 32768
#define RTB  128           // router tokens per block
#define FFNBLK 148         // persistent ffn grid (1 per SM)

// smem row strides (elements) — odd multiples of 8 -> conflict-free ldmatrix
#define XS   88
#define W1S  72
#define W2S  88

// ffn smem layout (bytes)
#define SM_SB1   0                              // 320 floats
#define SM_SB2   1280                           // 80 floats
#define SM_SCNT  1600                           // 8 ints
#define SM_TILE  1632                           // 1 int (+pad)
#define SM_XHI   1664
#define SM_XLO   (SM_XHI + TBK * XS * 2)        // 46720
#define SM_W1    (SM_XLO + TBK * XS * 2)        // 91776  (2 buffers)
#define W1HALF   (80 * W1S * 2)                 // 11520 (hi->lo offset)
#define W1BUF    (2 * W1HALF)                   // 23040 (buffer stride)
#define SM_W2    (SM_W1 + 2 * W1BUF)            // 137856 (2 buffers)
#define W2HALF   (64 * W2S * 2)                 // 11264
#define W2BUF    (2 * W2HALF)                   // 22528
#define SMEM_TOTAL (SM_W2 + 2 * W2BUF)          // 182912

// ---------------------------------------------------------------------------
// Scratch (no cudaMalloc allowed)
// ---------------------------------------------------------------------------
__device__ float    g_bufA[MAXT * D];           // combined activations
__device__ int      g_cnt[NL * E];              // per-layer expert counts
__device__ int      g_tctr;                     // dynamic tile counter
__device__ int      g_tok[E * MAXT];            // expert token lists
__device__ uint32_t g_sl [2 * MAXT];            // per-token (expert<<16)|slot
__device__ float    g_wtk[2 * MAXT];            // per-token top-2 weights
__device__ float    g_eo [2 * MAXT * D];        // expert outputs by global slot
// split-bf16 weights, natural layouts
__device__ __align__(16) unsigned short g_w1h[E * D * HID];   // [e][d][h]
__device__ __align__(16) unsigned short g_w1l[E * D * HID];
__device__ __align__(16) unsigned short g_w2h[E * HID * D];   // [e][h][d]
__device__ __align__(16) unsigned short g_w2l[E * HID * D];

// ---------------------------------------------------------------------------
// PTX helpers
// ---------------------------------------------------------------------------
__device__ __forceinline__ uint32_t smem_u32(const void* p) {
    uint32_t a;
    asm("{ .reg .u64 t; cvta.to.shared.u64 t, %1; cvt.u32.u64 %0, t; }" : "=r"(a) : "l"(p));
    return a;
}
__device__ __forceinline__ void ldsm4(uint32_t* r, uint32_t a) {
    asm volatile("ldmatrix.sync.aligned.m8n8.x4.shared.b16 {%0,%1,%2,%3}, [%4];"
        : "=r"(r[0]), "=r"(r[1]), "=r"(r[2]), "=r"(r[3]) : "r"(a));
}
__device__ __forceinline__ void ldsm4t(uint32_t* r, uint32_t a) {
    asm volatile("ldmatrix.sync.aligned.m8n8.x4.trans.shared.b16 {%0,%1,%2,%3}, [%4];"
        : "=r"(r[0]), "=r"(r[1]), "=r"(r[2]), "=r"(r[3]) : "r"(a));
}
__device__ __forceinline__ void mma_bf16(float* c, const uint32_t* a, const uint32_t* b) {
    asm volatile("mma.sync.aligned.m16n8k16.row.col.f32.bf16.bf16.f32 "
        "{%0,%1,%2,%3}, {%4,%5,%6,%7}, {%8,%9}, {%0,%1,%2,%3};"
        : "+f"(c[0]), "+f"(c[1]), "+f"(c[2]), "+f"(c[3])
        : "r"(a[0]), "r"(a[1]), "r"(a[2]), "r"(a[3]), "r"(b[0]), "r"(b[1]));
}
__device__ __forceinline__ void cpa16(uint32_t smem_dst, const void* gsrc) {
    asm volatile("cp.async.ca.shared.global [%0], [%1], 16;" :: "r"(smem_dst), "l"(gsrc));
}
#define CP_COMMIT() asm volatile("cp.async.commit_group;" ::: "memory")
#define CP_WAIT0()  asm volatile("cp.async.wait_group 0;" ::: "memory")

// ---------------------------------------------------------------------------
// Init kernels
// ---------------------------------------------------------------------------
__global__ void zero_kernel() {
    if (threadIdx.x < NL * E) g_cnt[threadIdx.x] = 0;
}
__global__ void prep_kernel(const float* __restrict__ W1, const float* __restrict__ W2) {
    int i = blockIdx.x * blockDim.x + threadIdx.x;
    const int N1 = E * D * HID;
    const int N2 = E * HID * D;
    if (i < N1) {
        float v = W1[i];
        __nv_bfloat16 h = __float2bfloat16(v);
        __nv_bfloat16 l = __float2bfloat16(v - __bfloat162float(h));
        g_w1h[i] = *(unsigned short*)&h;
        g_w1l[i] = *(unsigned short*)&l;
    } else if (i < N1 + N2) {
        int j = i - N1;
        float v = W2[j];
        __nv_bfloat16 h = __float2bfloat16(v);
        __nv_bfloat16 l = __float2bfloat16(v - __bfloat162float(h));
        g_w2h[j] = *(unsigned short*)&h;
        g_w2l[j] = *(unsigned short*)&l;
    }
}

// ---------------------------------------------------------------------------
// Router: (optionally) combine previous layer's expert outputs per token
// (fixed-order 2-term sum -> deterministic), then (optionally) route.
// Also resets the ffn tile counter. mode bit0 = combine, bit1 = route.
// ---------------------------------------------------------------------------
__global__ void __launch_bounds__(RTB)
router_kernel(const float* __restrict__ xin,
              const int* __restrict__ cntPrev,
              int* __restrict__ cntCur,
              float* __restrict__ xout,
              const float* __restrict__ Wg,
              const float* __restrict__ bg,
              int T, int mode) {
    __shared__ float wg[D * E];
    __shared__ float bgs[E];
    __shared__ float xs[RTB * 81];
    __shared__ int   pfx[E];
    __shared__ int   lcnt[E], gbase[E];

    int tid  = threadIdx.x;
    int base = blockIdx.x * RTB;
    if (blockIdx.x == 0 && tid == 0) g_tctr = 0;   // reset ffn tile counter
    int ntok = T - base; if (ntok > RTB) ntok = RTB;
    if (ntok <= 0) return;
    bool doComb  = (mode & 1) != 0;
    bool doRoute = (mode & 2) != 0;

    if (doRoute) {
        for (int i = tid; i < D * E; i += RTB) wg[i] = Wg[i];
        if (tid < E) bgs[tid] = bg[tid];
    }
    if (tid < E) lcnt[tid] = 0;
    if (doComb && tid == 0) {
        int a = 0;
        for (int e = 0; e < E; e++) { pfx[e] = a; a += cntPrev[e]; }
    }
    __syncthreads();

    if (doComb) {
        #pragma unroll
        for (int pass = 0; pass < 4; pass++) {
            int r = pass * 32 + (tid >> 2);
            if (r < ntok) {
                int t = base + r;
                uint32_t s0 = g_sl[2 * t], s1 = g_sl[2 * t + 1];
                float w0 = g_wtk[2 * t], w1 = g_wtk[2 * t + 1];
                const float* r0 = g_eo + (size_t)(pfx[s0 >> 16] + (int)(s0 & 0xFFFF)) * D;
                const float* r1 = g_eo + (size_t)(pfx[s1 >> 16] + (int)(s1 & 0xFFFF)) * D;
                float* xo = xout + (size_t)t * D;
                int sub = tid & 3;
                #pragma unroll
                for (int j = 0; j < 5; j++) {
                    int c = sub * 4 + j * 16;
                    float4 a = *(const float4*)&r0[c];
                    float4 b = *(const float4*)&r1[c];
                    float4 v;
                    v.x = w0 * a.x + w1 * b.x;
                    v.y = w0 * a.y + w1 * b.y;
                    v.z = w0 * a.z + w1 * b.z;
                    v.w = w0 * a.w + w1 * b.w;
                    *(float4*)&xo[c] = v;
                    float* dst = &xs[r * 81 + c];
                    dst[0] = v.x; dst[1] = v.y; dst[2] = v.z; dst[3] = v.w;
                }
            }
        }
    } else {
        const float4* gx = (const float4*)(xin + (size_t)base * D);
        int n4 = ntok * (D / 4);
        for (int i = tid; i < n4; i += RTB) {
            float4 v = gx[i];
            int r = i / 20, c = (i - r * 20) * 4;
            float* dst = &xs[r * 81 + c];
            dst[0] = v.x; dst[1] = v.y; dst[2] = v.z; dst[3] = v.w;
        }
    }
    __syncthreads();

    if (!doRoute) return;

    int   i0 = 0, i1 = 0, lp0 = 0, lp1 = 0;
    float v0 = -INFINITY, v1 = -INFINITY;
    if (tid < ntok) {
        float acc[E];
        #pragma unroll
        for (int e = 0; e < E; e++) acc[e] = bgs[e];
        const float* xr = &xs[tid * 81];
        #pragma unroll 4
        for (int k = 0; k < D; k++) {
            float xv = xr[k];
            #pragma unroll
            for (int e = 0; e < E; e++) acc[e] = fmaf(xv, wg[k * E + e], acc[e]);
        }
        #pragma unroll
        for (int e = 0; e < E; e++) {
            float v = acc[e];
            if (v > v0)      { v1 = v0; i1 = i0; v0 = v; i0 = e; }
            else if (v > v1) { v1 = v;  i1 = e; }
        }
        lp0 = atomicAdd(&lcnt[i0], 1);
        lp1 = atomicAdd(&lcnt[i1], 1);
    }
    __syncthreads();
    if (tid < E) gbase[tid] = atomicAdd(&cntCur[tid], lcnt[tid]);
    __syncthreads();
    if (tid < ntok) {
        int t = base + tid;
        int slot0 = gbase[i0] + lp0;
        int slot1 = gbase[i1] + lp1;
        g_tok[i0 * MAXT + slot0] = t;
        g_tok[i1 * MAXT + slot1] = t;
        g_sl[2 * t]     = ((uint32_t)i0 << 16) | (uint32_t)slot0;
        g_sl[2 * t + 1] = ((uint32_t)i1 << 16) | (uint32_t)slot1;
        g_wtk[2 * t]     = v0;
        g_wtk[2 * t + 1] = v1;
    }
}

// ---------------------------------------------------------------------------
// FFN: one persistent 512-thread block per SM pulls 256-token tiles.
// 16 warps, each owns 16 M-rows and the FULL N. Double-buffered W1/W2 tiles:
// ONE __syncthreads + ONE cp.async wait per chunk; next chunk's W1+W2 loads
// issue right after the register convert and overlap GEMM2 + next GEMM1.
// GEMM1 C-fragments convert in registers into GEMM2 A-fragments (no H smem).
// ---------------------------------------------------------------------------
__global__ void __launch_bounds__(512, 1)
ffn_kernel(const float* __restrict__ in,
           const int* __restrict__ cnt,
           const float* __restrict__ b1,  const float* __restrict__ b2) {
    extern __shared__ char smem[];
    uint32_t sb = smem_u32(smem);
    int tid  = threadIdx.x;
    int lane = tid & 31;
    int wid  = tid >> 5;

    int*   scnt  = (int*)(smem + SM_SCNT);
    int*   stile = (int*)(smem + SM_TILE);
    float* sb1a  = (float*)(smem + SM_SB1);
    float* sb2   = (float*)(smem + SM_SB2);

    if (tid < E) scnt[tid] = cnt[tid];
    __syncthreads();

    int ntiles = 0;
    {
        int acc = 0;
        #pragma unroll
        for (int ee = 0; ee < E; ee++) acc += (scnt[ee] + TBK - 1) >> 8;
        ntiles = acc;
    }

    // per-thread constant addresses (buffer 0 bases)
    uint32_t aX  = sb + SM_XHI + (((wid << 4) + (lane & 15)) * XS + (lane >> 4) * 8) * 2;
    uint32_t bW1 = sb + SM_W1  + ((lane & 15) * W1S + (lane >> 4) * 8) * 2;
    uint32_t bW2 = sb + SM_W2  + ((lane & 15) * W2S + (lane >> 4) * 8) * 2;
    const int dXlo = SM_XLO - SM_XHI;
    int bcol = (lane & 3) * 2;

    for (;;) {
        if (tid == 0) *stile = atomicAdd(&g_tctr, 1);
        __syncthreads();            // broadcast tile; fences prev-tile smem reuse
        int tile = *stile;
        if (tile >= ntiles) break;

        // map tile -> (expert, start, slot prefix base)
        int e = 0, start = 0, pbase = 0, n = 0;
        {
            int accB = 0, accN = 0;
            #pragma unroll
            for (int ee = 0; ee < E; ee++) {
                int ne = scnt[ee];
                int bl = (ne + TBK - 1) >> 8;
                if (tile >= accB && tile < accB + bl) {
                    e = ee; start = (tile - accB) * TBK; pbase = accN; n = ne;
                }
                accB += bl; accN += ne;
            }
        }

        const unsigned short* w1hB = g_w1h + e * D * HID;
        const unsigned short* w1lB = g_w1l + e * D * HID;
        const unsigned short* w2hB = g_w2h + e * HID * D;
        const unsigned short* w2lB = g_w2l + e * HID * D;

        // cp.async weight staging into buffer `bf` (640 x 16B per hi/lo array)
        #define ISSUE_W1(c, bf) { \
            uint32_t d0 = sb + SM_W1 + (bf) * W1BUF; \
            { int idx = tid; int row = idx >> 3, v = idx & 7; \
              cpa16(d0 +          (row * W1S + v * 8) * 2, w1hB + (c) * 64 + row * HID + v * 8); \
              cpa16(d0 + W1HALF + (row * W1S + v * 8) * 2, w1lB + (c) * 64 + row * HID + v * 8); } \
            if (tid < 128) { int idx = tid + 512; int row = idx >> 3, v = idx & 7; \
              cpa16(d0 +          (row * W1S + v * 8) * 2, w1hB + (c) * 64 + row * HID + v * 8); \
              cpa16(d0 + W1HALF + (row * W1S + v * 8) * 2, w1lB + (c) * 64 + row * HID + v * 8); } }
        #define ISSUE_W2(c, bf) { \
            uint32_t d0 = sb + SM_W2 + (bf) * W2BUF; \
            { int idx = tid; int row = idx / 10, v = idx - row * 10; \
              cpa16(d0 +          (row * W2S + v * 8) * 2, w2hB + (c) * 64 * D + row * D + v * 8); \
              cpa16(d0 + W2HALF + (row * W2S + v * 8) * 2, w2lB + (c) * 64 * D + row * D + v * 8); } \
            if (tid < 128) { int idx = tid + 512; int row = idx / 10, v = idx - row * 10; \
              cpa16(d0 +          (row * W2S + v * 8) * 2, w2hB + (c) * 64 * D + row * D + v * 8); \
              cpa16(d0 + W2HALF + (row * W2S + v * 8) * 2, w2lB + (c) * 64 * D + row * D + v * 8); } }

        ISSUE_W1(0, 0);
        ISSUE_W2(0, 0);
        CP_COMMIT();

        // ---- gather X, split into bf16 hi/lo smem (2 threads per token) ----
        {
            int r = tid >> 1, half = tid & 1;
            int tk = (start + r < n) ? g_tok[e * MAXT + start + r] : -1;
            const float* xr = in + (size_t)(tk < 0 ? 0 : tk) * D + half * 40;
            char* dh = smem + SM_XHI + (r * XS + half * 40) * 2;
            char* dl = smem + SM_XLO + (r * XS + half * 40) * 2;
            #pragma unroll
            for (int j = 0; j < 20; j++) {
                float2 v = (tk >= 0) ? *(const float2*)&xr[2 * j] : make_float2(0.f, 0.f);
                __nv_bfloat162 h2 = __floats2bfloat162_rn(v.x, v.y);
                float2 hf = __bfloat1622float2(h2);
                __nv_bfloat162 l2 = __floats2bfloat162_rn(v.x - hf.x, v.y - hf.y);
                *(uint32_t*)(dh + 4 * j) = *(uint32_t*)&h2;
                *(uint32_t*)(dl + 4 * j) = *(uint32_t*)&l2;
            }
        }
        for (int i = tid; i < HID; i += 512) sb1a[i] = b1[e * HID + i];
        if (tid < D) sb2[tid] = b2[e * D + tid];

        float yacc[10][4];
        #pragma unroll
        for (int na = 0; na < 10; na++)
            #pragma unroll
            for (int i = 0; i < 4; i++) yacc[na][i] = 0.f;

        #pragma unroll
        for (int c = 0; c < NCK; c++) {
            uint32_t bW1c = bW1 + (uint32_t)(c & 1) * W1BUF;
            uint32_t bW2c = bW2 + (uint32_t)(c & 1) * W2BUF;

            CP_WAIT0();          // this chunk's W1+W2 copies complete (per-thread)
            __syncthreads();     // ... and visible block-wide (X/biases too at c=0)

            // ---- GEMM1: acc = X(16x80) @ W1chunk(80x64), 3-term split ----
            float acc[8][4];
            #pragma unroll
            for (int na = 0; na < 8; na++)
                #pragma unroll
                for (int i = 0; i < 4; i++) acc[na][i] = 0.f;

            #pragma unroll
            for (int ks = 0; ks < 5; ks++) {
                uint32_t ah[4], al[4];
                ldsm4(ah, aX + ks * 32);
                ldsm4(al, aX + ks * 32 + dXlo);
                #pragma unroll
                for (int np = 0; np < 4; np++) {
                    uint32_t ba = bW1c + (ks * 16 * W1S + np * 16) * 2;
                    uint32_t bh[4], bl[4];
                    ldsm4t(bh, ba);
                    ldsm4t(bl, ba + W1HALF);
                    mma_bf16(acc[2 * np],     ah, bh);
                    mma_bf16(acc[2 * np],     ah, bl);
                    mma_bf16(acc[2 * np],     al, bh);
                    mma_bf16(acc[2 * np + 1], ah, bh + 2);
                    mma_bf16(acc[2 * np + 1], ah, bl + 2);
                    mma_bf16(acc[2 * np + 1], al, bh + 2);
                }
            }

            // ---- convert in registers: H = relu(acc + b1) -> A-fragments ----
            uint32_t ha[4][4], la[4][4];
            #pragma unroll
            for (int kp = 0; kp < 4; kp++) {
                #pragma unroll
                for (int j = 0; j < 2; j++) {
                    int na = 2 * kp + j;
                    const float* bp = &sb1a[c * 64 + 8 * na + bcol];
                    float bb0 = bp[0], bb1 = bp[1];
                    float f0 = fmaxf(acc[na][0] + bb0, 0.f);
                    float f1 = fmaxf(acc[na][1] + bb1, 0.f);
                    float f2 = fmaxf(acc[na][2] + bb0, 0.f);
                    float f3 = fmaxf(acc[na][3] + bb1, 0.f);
                    __nv_bfloat162 h01 = __floats2bfloat162_rn(f0, f1);
                    float2 hf01 = __bfloat1622float2(h01);
                    __nv_bfloat162 l01 = __floats2bfloat162_rn(f0 - hf01.x, f1 - hf01.y);
                    __nv_bfloat162 h23 = __floats2bfloat162_rn(f2, f3);
                    float2 hf23 = __bfloat1622float2(h23);
                    __nv_bfloat162 l23 = __floats2bfloat162_rn(f2 - hf23.x, f3 - hf23.y);
                    ha[kp][2 * j]     = *(uint32_t*)&h01;
                    ha[kp][2 * j + 1] = *(uint32_t*)&h23;
                    la[kp][2 * j]     = *(uint32_t*)&l01;
                    la[kp][2 * j + 1] = *(uint32_t*)&l23;
                }
            }

            // issue NEXT chunk's weights into the idle buffers (no sync needed:
            // their previous readers finished before this chunk's start barrier)
            if (c < NCK - 1) {
                ISSUE_W1(c + 1, (c + 1) & 1);
                ISSUE_W2(c + 1, (c + 1) & 1);
                CP_COMMIT();
            }

            // ---- GEMM2: yacc += H(16x64) @ W2chunk(64x80), 3-term split ----
            #pragma unroll
            for (int kp = 0; kp < 4; kp++) {
                #pragma unroll
                for (int nb = 0; nb < 5; nb++) {
                    uint32_t ba = bW2c + (kp * 16 * W2S + nb * 16) * 2;
                    uint32_t bh[4], bl[4];
                    ldsm4t(bh, ba);
                    ldsm4t(bl, ba + W2HALF);
                    mma_bf16(yacc[2 * nb],     ha[kp], bh);
                    mma_bf16(yacc[2 * nb],     ha[kp], bl);
                    mma_bf16(yacc[2 * nb],     la[kp], bh);
                    mma_bf16(yacc[2 * nb + 1], ha[kp], bh + 2);
                    mma_bf16(yacc[2 * nb + 1], ha[kp], bl + 2);
                    mma_bf16(yacc[2 * nb + 1], la[kp], bh + 2);
                }
            }
        }

        // ---- write expert-output rows (y + b2) to slot buffer, non-atomic ----
        {
            int row0 = (wid << 4) + (lane >> 2);
            int row1 = row0 + 8;
            bool v0 = (start + row0 < n);
            bool v1 = (start + row1 < n);
            float* o0 = g_eo + (size_t)(pbase + start + row0) * D;
            float* o1 = g_eo + (size_t)(pbase + start + row1) * D;
            #pragma unroll
            for (int nb = 0; nb < 10; nb++) {
                int col = 8 * nb + bcol;
                float b20 = sb2[col], b21 = sb2[col + 1];
                if (v0) *(float2*)&o0[col] = make_float2(yacc[nb][0] + b20, yacc[nb][1] + b21);
                if (v1) *(float2*)&o1[col] = make_float2(yacc[nb][2] + b20, yacc[nb][3] + b21);
            }
        }
        #undef ISSUE_W1
        #undef ISSUE_W2
    }
}

// ---------------------------------------------------------------------------
extern "C" void kernel_launch(void* const* d_in, const int* in_sizes, int n_in,
                              void* d_out, int out_size) {
    const float* x  = (const float*)d_in[0];
    const float* Wg = (const float*)d_in[1];
    const float* bg = (const float*)d_in[2];
    const float* W1 = (const float*)d_in[3];
    const float* b1 = (const float*)d_in[4];
    const float* W2 = (const float*)d_in[5];
    const float* b2 = (const float*)d_in[6];
    float* out = (float*)d_out;

    int T = in_sizes[0] / D;

    cudaFuncSetAttribute(ffn_kernel, cudaFuncAttributeMaxDynamicSharedMemorySize, SMEM_TOTAL);

    void *cntp, *bufAp;
    cudaGetSymbolAddress(&cntp,  g_cnt);
    cudaGetSymbolAddress(&bufAp, g_bufA);
    int*   cntb = (int*)cntp;
    float* bufA = (float*)bufAp;

    const int NPREP = E * D * HID + E * HID * D;   // 409600
    prep_kernel<<<(NPREP + 255) / 256, 256>>>(W1, W2);
    zero_kernel<<<1, 64>>>();

    int rb = (T + RTB - 1) / RTB;

    for (int l = 0; l < NL; l++) {
        int mode = (l == 0) ? 2 : 3;
        router_kernel<<<rb, RTB>>>((l == 0) ? x : nullptr,
                                   cntb + (l - 1) * E,
                                   cntb + l * E,
                                   bufA,
                                   Wg + (size_t)l * D * E, bg + l * E,
                                   T, mode);
        ffn_kernel<<<FFNBLK, 512, SMEM_TOTAL>>>((l == 0) ? x : bufA,
                                                cntb + l * E, b1, b2);
    }
    // final combine-only pass -> d_out
    router_kernel<<<rb, RTB>>>(nullptr, cntb + (NL - 1) * E, cntb, out,
                               Wg, bg, T, 1);
}

// round 14
// speedup vs baseline: 1.2983x; 1.2983x over previous
#include <cuda_runtime.h>
#include <cuda_bf16.h>
#include <math.h>
#include <stdint.h>

// Problem constants
#define D    80
#define E    8
#define HID  320
#define NL   4
#define TBK  128           // tokens per ffn tile
#define NCK  5             // HID chunks of 64
#define MAXT 32768
#define RTB  128           // router tokens per block
#define FFNBLK 296         // persistent ffn grid (2 per SM)

// smem row strides (elements) — odd multiples of 8 -> conflict-free ldmatrix
#define XS   88
#define W1S  72
#define W2S  88

#define W1HALF (80 * W1S * 2)     // 11520  hi->lo offset inside W1 image
#define W1BUF  (2 * W1HALF)       // 23040  full W1 chunk image (hi||lo)
#define W2HALF (64 * W2S * 2)     // 11264
#define W2BUF  (2 * W2HALF)       // 22528

// ffn smem layout (bytes)
#define SM_SB1   0                            // 320 floats
#define SM_SB2   1280                         // 80 floats
#define SM_SCNT  1600                         // 8 ints
#define SM_TILE  1632                         // 1 int
#define SM_MB1   1640                         // mbarrier (8B)
#define SM_MB2   1648                         // mbarrier (8B)
#define SM_XHI   1664
#define SM_XLO   (SM_XHI + TBK * XS * 2)      // 24192
#define SM_W1    (SM_XLO + TBK * XS * 2)      // 46720
#define SM_W2    (SM_W1 + W1BUF)              // 69760
#define SMEM_TOTAL (SM_W2 + W2BUF)            // 92288

// ---------------------------------------------------------------------------
// Scratch (no cudaMalloc allowed)
// ---------------------------------------------------------------------------
__device__ float    g_bufA[MAXT * D];           // combined activations
__device__ int      g_cnt[NL * E];              // per-layer expert counts
__device__ int      g_tctr;                     // dynamic tile counter
__device__ int      g_tok[E * MAXT];            // expert token lists
__device__ uint32_t g_sl [2 * MAXT];            // per-token (expert<<16)|slot
__device__ float    g_wtk[2 * MAXT];            // per-token top-2 weights
__device__ float    g_eo [2 * MAXT * D];        // expert outputs by global slot
// pre-padded smem images of split-bf16 weight chunks: [e][c] hi || lo
__device__ __align__(16) unsigned short g_w1img2[E * NCK * (W1BUF / 2)];
__device__ __align__(16) unsigned short g_w2img2[E * NCK * (W2BUF / 2)];

// ---------------------------------------------------------------------------
// PTX helpers
// ---------------------------------------------------------------------------
__device__ __forceinline__ uint32_t smem_u32(const void* p) {
    uint32_t a;
    asm("{ .reg .u64 t; cvta.to.shared.u64 t, %1; cvt.u32.u64 %0, t; }" : "=r"(a) : "l"(p));
    return a;
}
__device__ __forceinline__ void ldsm4(uint32_t* r, uint32_t a) {
    asm volatile("ldmatrix.sync.aligned.m8n8.x4.shared.b16 {%0,%1,%2,%3}, [%4];"
        : "=r"(r[0]), "=r"(r[1]), "=r"(r[2]), "=r"(r[3]) : "r"(a));
}
__device__ __forceinline__ void ldsm4t(uint32_t* r, uint32_t a) {
    asm volatile("ldmatrix.sync.aligned.m8n8.x4.trans.shared.b16 {%0,%1,%2,%3}, [%4];"
        : "=r"(r[0]), "=r"(r[1]), "=r"(r[2]), "=r"(r[3]) : "r"(a));
}
__device__ __forceinline__ void mma_bf16(float* c, const uint32_t* a, const uint32_t* b) {
    asm volatile("mma.sync.aligned.m16n8k16.row.col.f32.bf16.bf16.f32 "
        "{%0,%1,%2,%3}, {%4,%5,%6,%7}, {%8,%9}, {%0,%1,%2,%3};"
        : "+f"(c[0]), "+f"(c[1]), "+f"(c[2]), "+f"(c[3])
        : "r"(a[0]), "r"(a[1]), "r"(a[2]), "r"(a[3]), "r"(b[0]), "r"(b[1]));
}
// TMA-engine 1D bulk copy global -> shared, mbarrier completion (sm_90+)
__device__ __forceinline__ void bulkcp(uint32_t dst, const void* src,
                                       uint32_t bytes, uint32_t mbar) {
    asm volatile("cp.async.bulk.shared::cluster.global.mbarrier::complete_tx::bytes "
                 "[%0], [%1], %2, [%3];"
        :: "r"(dst), "l"(src), "r"(bytes), "r"(mbar) : "memory");
}
#define MBARRIER_INIT(mbar, cnt) \
    asm volatile("mbarrier.init.shared.b64 [%0], %1;" :: "r"((uint32_t)(mbar)), "r"((uint32_t)(cnt)) : "memory")
#define MB_EXPECT(mbar, bytes) \
    asm volatile("mbarrier.arrive.expect_tx.shared.b64 _, [%0], %1;" :: "r"((uint32_t)(mbar)), "r"((uint32_t)(bytes)) : "memory")
#define FENCE_PROXY_ASYNC() asm volatile("fence.proxy.async.shared::cta;" ::: "memory")
#define MB_WAIT(mbar, par) do { \
    uint32_t _m = (uint32_t)(mbar); uint32_t _p = (uint32_t)(par); uint32_t _d; \
    asm volatile("{\n\t.reg .pred p;\n\tmbarrier.try_wait.parity.acquire.cta.shared::cta.b64 p, [%1], %2;\n\tselp.b32 %0, 1, 0, p;\n\t}" \
        : "=r"(_d) : "r"(_m), "r"(_p) : "memory"); \
    if (!_d) { \
        asm volatile("{\n\t.reg .pred P1;\n\tWL_%=:\n\tmbarrier.try_wait.parity.acquire.cta.shared::cta.b64 P1, [%0], %1, 0x989680;\n\t@P1 bra.uni WD_%=;\n\tbra.uni WL_%=;\n\tWD_%=:\n\t}" \
            :: "r"(_m), "r"(_p) : "memory"); \
    } } while (0)

// ---------------------------------------------------------------------------
// Init kernels
// ---------------------------------------------------------------------------
__global__ void zero_kernel() {
    if (threadIdx.x < NL * E) g_cnt[threadIdx.x] = 0;
}
// Prep: split fp32 -> bf16 hi/lo, write pre-padded smem images per (e,chunk)
__global__ void prep_kernel(const float* __restrict__ W1, const float* __restrict__ W2) {
    int i = blockIdx.x * blockDim.x + threadIdx.x;
    const int N1 = E * NCK * 80 * 64;   // 204800
    const int N2 = E * NCK * 64 * 80;   // 204800
    if (i < N1) {
        int col = i & 63;
        int t = i >> 6;
        int row = t % 80;  t /= 80;
        int c = t % NCK;   int e = t / NCK;
        float v = W1[(e * D + row) * HID + c * 64 + col];
        __nv_bfloat16 h = __float2bfloat16(v);
        __nv_bfloat16 l = __float2bfloat16(v - __bfloat162float(h));
        int base = (e * NCK + c) * (W1BUF / 2) + row * W1S + col;
        g_w1img2[base]               = *(unsigned short*)&h;
        g_w1img2[base + W1HALF / 2]  = *(unsigned short*)&l;
    } else if (i < N1 + N2) {
        int j = i - N1;
        int col = j % 80;
        int t = j / 80;
        int row = t % 64;  t /= 64;
        int c = t % NCK;   int e = t / NCK;
        float v = W2[(e * HID + c * 64 + row) * D + col];
        __nv_bfloat16 h = __float2bfloat16(v);
        __nv_bfloat16 l = __float2bfloat16(v - __bfloat162float(h));
        int base = (e * NCK + c) * (W2BUF / 2) + row * W2S + col;
        g_w2img2[base]               = *(unsigned short*)&h;
        g_w2img2[base + W2HALF / 2]  = *(unsigned short*)&l;
    }
}

// ---------------------------------------------------------------------------
// Router: (optionally) combine previous layer's expert outputs per token
// (fixed-order 2-term sum -> deterministic), then (optionally) route.
// Also resets the ffn tile counter. mode bit0 = combine, bit1 = route.
// ---------------------------------------------------------------------------
__global__ void __launch_bounds__(RTB)
router_kernel(const float* __restrict__ xin,
              const int* __restrict__ cntPrev,
              int* __restrict__ cntCur,
              float* __restrict__ xout,
              const float* __restrict__ Wg,
              const float* __restrict__ bg,
              int T, int mode) {
    __shared__ float wg[D * E];
    __shared__ float bgs[E];
    __shared__ float xs[RTB * 81];
    __shared__ int   pfx[E];
    __shared__ int   lcnt[E], gbase[E];

    int tid  = threadIdx.x;
    int base = blockIdx.x * RTB;
    if (blockIdx.x == 0 && tid == 0) g_tctr = 0;   // reset ffn tile counter
    int ntok = T - base; if (ntok > RTB) ntok = RTB;
    if (ntok <= 0) return;
    bool doComb  = (mode & 1) != 0;
    bool doRoute = (mode & 2) != 0;

    if (doRoute) {
        for (int i = tid; i < D * E; i += RTB) wg[i] = Wg[i];
        if (tid < E) bgs[tid] = bg[tid];
    }
    if (tid < E) lcnt[tid] = 0;
    if (doComb && tid == 0) {
        int a = 0;
        for (int e = 0; e < E; e++) { pfx[e] = a; a += cntPrev[e]; }
    }
    __syncthreads();

    if (doComb) {
        #pragma unroll
        for (int pass = 0; pass < 4; pass++) {
            int r = pass * 32 + (tid >> 2);
            if (r < ntok) {
                int t = base + r;
                uint32_t s0 = g_sl[2 * t], s1 = g_sl[2 * t + 1];
                float w0 = g_wtk[2 * t], w1 = g_wtk[2 * t + 1];
                const float* r0 = g_eo + (size_t)(pfx[s0 >> 16] + (int)(s0 & 0xFFFF)) * D;
                const float* r1 = g_eo + (size_t)(pfx[s1 >> 16] + (int)(s1 & 0xFFFF)) * D;
                float* xo = xout + (size_t)t * D;
                int sub = tid & 3;
                #pragma unroll
                for (int j = 0; j < 5; j++) {
                    int c = sub * 4 + j * 16;
                    float4 a = *(const float4*)&r0[c];
                    float4 b = *(const float4*)&r1[c];
                    float4 v;
                    v.x = w0 * a.x + w1 * b.x;
                    v.y = w0 * a.y + w1 * b.y;
                    v.z = w0 * a.z + w1 * b.z;
                    v.w = w0 * a.w + w1 * b.w;
                    *(float4*)&xo[c] = v;
                    float* dst = &xs[r * 81 + c];
                    dst[0] = v.x; dst[1] = v.y; dst[2] = v.z; dst[3] = v.w;
                }
            }
        }
    } else {
        const float4* gx = (const float4*)(xin + (size_t)base * D);
        int n4 = ntok * (D / 4);
        for (int i = tid; i < n4; i += RTB) {
            float4 v = gx[i];
            int r = i / 20, c = (i - r * 20) * 4;
            float* dst = &xs[r * 81 + c];
            dst[0] = v.x; dst[1] = v.y; dst[2] = v.z; dst[3] = v.w;
        }
    }
    __syncthreads();

    if (!doRoute) return;

    int   i0 = 0, i1 = 0, lp0 = 0, lp1 = 0;
    float v0 = -INFINITY, v1 = -INFINITY;
    if (tid < ntok) {
        float acc[E];
        #pragma unroll
        for (int e = 0; e < E; e++) acc[e] = bgs[e];
        const float* xr = &xs[tid * 81];
        #pragma unroll 4
        for (int k = 0; k < D; k++) {
            float xv = xr[k];
            #pragma unroll
            for (int e = 0; e < E; e++) acc[e] = fmaf(xv, wg[k * E + e], acc[e]);
        }
        #pragma unroll
        for (int e = 0; e < E; e++) {
            float v = acc[e];
            if (v > v0)      { v1 = v0; i1 = i0; v0 = v; i0 = e; }
            else if (v > v1) { v1 = v;  i1 = e; }
        }
        lp0 = atomicAdd(&lcnt[i0], 1);
        lp1 = atomicAdd(&lcnt[i1], 1);
    }
    __syncthreads();
    if (tid < E) gbase[tid] = atomicAdd(&cntCur[tid], lcnt[tid]);
    __syncthreads();
    if (tid < ntok) {
        int t = base + tid;
        int slot0 = gbase[i0] + lp0;
        int slot1 = gbase[i1] + lp1;
        g_tok[i0 * MAXT + slot0] = t;
        g_tok[i1 * MAXT + slot1] = t;
        g_sl[2 * t]     = ((uint32_t)i0 << 16) | (uint32_t)slot0;
        g_sl[2 * t + 1] = ((uint32_t)i1 << 16) | (uint32_t)slot1;
        g_wtk[2 * t]     = v0;
        g_wtk[2 * t + 1] = v1;
    }
}

// ---------------------------------------------------------------------------
// FFN: persistent blocks (2/SM) dynamically pull 128-token tiles.
// Weight chunk staging = ONE cp.async.bulk per array per chunk (TMA engine,
// zero LSU cost) with mbarrier completion; pre-padded images from prep.
// 8 warps; each owns 16 M-rows and the FULL N; register H-fragments.
// ---------------------------------------------------------------------------
__global__ void __launch_bounds__(256, 2)
ffn_kernel(const float* __restrict__ in,
           const int* __restrict__ cnt,
           const float* __restrict__ b1,  const float* __restrict__ b2) {
    extern __shared__ char smem[];
    uint32_t sb = smem_u32(smem);
    int tid  = threadIdx.x;
    int lane = tid & 31;
    int wid  = tid >> 5;

    int*   scnt  = (int*)(smem + SM_SCNT);
    int*   stile = (int*)(smem + SM_TILE);
    float* sb1a  = (float*)(smem + SM_SB1);
    float* sb2   = (float*)(smem + SM_SB2);
    uint32_t mb1 = sb + SM_MB1;
    uint32_t mb2 = sb + SM_MB2;

    if (tid == 0) {
        MBARRIER_INIT(mb1, 1);
        MBARRIER_INIT(mb2, 1);
        FENCE_PROXY_ASYNC();
    }
    if (tid < E) scnt[tid] = cnt[tid];
    __syncthreads();

    int ntiles = 0;
    {
        int acc = 0;
        #pragma unroll
        for (int ee = 0; ee < E; ee++) acc += (scnt[ee] + TBK - 1) >> 7;
        ntiles = acc;
    }

    // per-thread constant addresses
    uint32_t aX  = sb + SM_XHI + (((wid << 4) + (lane & 15)) * XS + (lane >> 4) * 8) * 2;
    uint32_t bW1 = sb + SM_W1  + ((lane & 15) * W1S + (lane >> 4) * 8) * 2;
    uint32_t bW2 = sb + SM_W2  + ((lane & 15) * W2S + (lane >> 4) * 8) * 2;
    const int dXlo = SM_XLO - SM_XHI;
    int bcol = (lane & 3) * 2;

    uint32_t p1 = 0, p2 = 0;    // mbarrier phase parities (all threads in sync)

    for (;;) {
        if (tid == 0) *stile = atomicAdd(&g_tctr, 1);
        __syncthreads();            // broadcast tile; fences prev-tile smem reuse
        int tile = *stile;
        if (tile >= ntiles) break;

        // map tile -> (expert, start, slot prefix base)
        int e = 0, start = 0, pbase = 0, n = 0;
        {
            int accB = 0, accN = 0;
            #pragma unroll
            for (int ee = 0; ee < E; ee++) {
                int ne = scnt[ee];
                int bl = (ne + TBK - 1) >> 7;
                if (tile >= accB && tile < accB + bl) {
                    e = ee; start = (tile - accB) * TBK; pbase = accN; n = ne;
                }
                accB += bl; accN += ne;
            }
        }

        const unsigned short* w1img = g_w1img2 + (size_t)e * NCK * (W1BUF / 2);
        const unsigned short* w2img = g_w2img2 + (size_t)e * NCK * (W2BUF / 2);

        // kick off chunk-0 weight copies on the TMA engine
        if (tid == 0) {
            MB_EXPECT(mb1, W1BUF);
            bulkcp(sb + SM_W1, w1img, W1BUF, mb1);
            MB_EXPECT(mb2, W2BUF);
            bulkcp(sb + SM_W2, w2img, W2BUF, mb2);
        }

        // ---- gather X, split into bf16 hi/lo smem (2 threads per token) ----
        {
            int r = tid >> 1, half = tid & 1;
            int tk = (start + r < n) ? g_tok[e * MAXT + start + r] : -1;
            const float* xr = in + (size_t)(tk < 0 ? 0 : tk) * D + half * 40;
            char* dh = smem + SM_XHI + (r * XS + half * 40) * 2;
            char* dl = smem + SM_XLO + (r * XS + half * 40) * 2;
            #pragma unroll
            for (int jq = 0; jq < 5; jq++) {
                float4 va, vb;
                if (tk >= 0) {
                    va = *(const float4*)&xr[8 * jq];
                    vb = *(const float4*)&xr[8 * jq + 4];
                } else {
                    va = make_float4(0.f, 0.f, 0.f, 0.f);
                    vb = va;
                }
                uint4 vh, vl;
                uint32_t* ph = (uint32_t*)&vh;
                uint32_t* pl = (uint32_t*)&vl;
                float fx[8] = {va.x, va.y, va.z, va.w, vb.x, vb.y, vb.z, vb.w};
                #pragma unroll
                for (int k = 0; k < 4; k++) {
                    __nv_bfloat162 h2 = __floats2bfloat162_rn(fx[2 * k], fx[2 * k + 1]);
                    float2 hf = __bfloat1622float2(h2);
                    __nv_bfloat162 l2 = __floats2bfloat162_rn(fx[2 * k] - hf.x, fx[2 * k + 1] - hf.y);
                    ph[k] = *(uint32_t*)&h2;
                    pl[k] = *(uint32_t*)&l2;
                }
                *(uint4*)(dh + 16 * jq) = vh;
                *(uint4*)(dl + 16 * jq) = vl;
            }
        }
        for (int i = tid; i < HID; i += 256) sb1a[i] = b1[e * HID + i];
        if (tid < D) sb2[tid] = b2[e * D + tid];
        __syncthreads();     // X + biases visible block-wide

        float yacc[10][4];
        #pragma unroll
        for (int na = 0; na < 10; na++)
            #pragma unroll
            for (int i = 0; i < 4; i++) yacc[na][i] = 0.f;

        #pragma unroll
        for (int c = 0; c < NCK; c++) {
            MB_WAIT(mb1, p1); p1 ^= 1;    // W1[c] image arrived

            // ---- GEMM1: acc = X(16x80) @ W1chunk(80x64), 3-term split ----
            float acc[8][4];
            #pragma unroll
            for (int na = 0; na < 8; na++)
                #pragma unroll
                for (int i = 0; i < 4; i++) acc[na][i] = 0.f;

            #pragma unroll
            for (int ks = 0; ks < 5; ks++) {
                uint32_t ah[4], al[4];
                ldsm4(ah, aX + ks * 32);
                ldsm4(al, aX + ks * 32 + dXlo);
                #pragma unroll
                for (int np = 0; np < 4; np++) {
                    uint32_t ba = bW1 + (ks * 16 * W1S + np * 16) * 2;
                    uint32_t bh[4], bl[4];
                    ldsm4t(bh, ba);
                    ldsm4t(bl, ba + W1HALF);
                    mma_bf16(acc[2 * np],     ah, bh);
                    mma_bf16(acc[2 * np],     ah, bl);
                    mma_bf16(acc[2 * np],     al, bh);
                    mma_bf16(acc[2 * np + 1], ah, bh + 2);
                    mma_bf16(acc[2 * np + 1], ah, bl + 2);
                    mma_bf16(acc[2 * np + 1], al, bh + 2);
                }
            }

            // ---- convert in registers: H = relu(acc + b1) -> A-fragments ----
            uint32_t ha[4][4], la[4][4];
            #pragma unroll
            for (int kp = 0; kp < 4; kp++) {
                #pragma unroll
                for (int j = 0; j < 2; j++) {
                    int na = 2 * kp + j;
                    const float* bp = &sb1a[c * 64 + 8 * na + bcol];
                    float bb0 = bp[0], bb1 = bp[1];
                    float f0 = fmaxf(acc[na][0] + bb0, 0.f);
                    float f1 = fmaxf(acc[na][1] + bb1, 0.f);
                    float f2 = fmaxf(acc[na][2] + bb0, 0.f);
                    float f3 = fmaxf(acc[na][3] + bb1, 0.f);
                    __nv_bfloat162 h01 = __floats2bfloat162_rn(f0, f1);
                    float2 hf01 = __bfloat1622float2(h01);
                    __nv_bfloat162 l01 = __floats2bfloat162_rn(f0 - hf01.x, f1 - hf01.y);
                    __nv_bfloat162 h23 = __floats2bfloat162_rn(f2, f3);
                    float2 hf23 = __bfloat1622float2(h23);
                    __nv_bfloat162 l23 = __floats2bfloat162_rn(f2 - hf23.x, f3 - hf23.y);
                    ha[kp][2 * j]     = *(uint32_t*)&h01;
                    ha[kp][2 * j + 1] = *(uint32_t*)&h23;
                    la[kp][2 * j]     = *(uint32_t*)&l01;
                    la[kp][2 * j + 1] = *(uint32_t*)&l23;
                }
            }

            __syncthreads();     // all warps done reading W1[c]
            if (c < NCK - 1 && tid == 0) {
                MB_EXPECT(mb1, W1BUF);
                bulkcp(sb + SM_W1, w1img + (size_t)(c + 1) * (W1BUF / 2), W1BUF, mb1);
            }

            MB_WAIT(mb2, p2); p2 ^= 1;    // W2[c] image arrived

            // ---- GEMM2: yacc += H(16x64) @ W2chunk(64x80), 3-term split ----
            #pragma unroll
            for (int kp = 0; kp < 4; kp++) {
                #pragma unroll
                for (int nb = 0; nb < 5; nb++) {
                    uint32_t ba = bW2 + (kp * 16 * W2S + nb * 16) * 2;
                    uint32_t bh[4], bl[4];
                    ldsm4t(bh, ba);
                    ldsm4t(bl, ba + W2HALF);
                    mma_bf16(yacc[2 * nb],     ha[kp], bh);
                    mma_bf16(yacc[2 * nb],     ha[kp], bl);
                    mma_bf16(yacc[2 * nb],     la[kp], bh);
                    mma_bf16(yacc[2 * nb + 1], ha[kp], bh + 2);
                    mma_bf16(yacc[2 * nb + 1], ha[kp], bl + 2);
                    mma_bf16(yacc[2 * nb + 1], la[kp], bh + 2);
                }
            }

            __syncthreads();     // all warps done reading W2[c]
            if (c < NCK - 1 && tid == 0) {
                MB_EXPECT(mb2, W2BUF);
                bulkcp(sb + SM_W2, w2img + (size_t)(c + 1) * (W2BUF / 2), W2BUF, mb2);
            }
        }

        // ---- write expert-output rows (y + b2) to slot buffer, non-atomic ----
        {
            int row0 = (wid << 4) + (lane >> 2);
            int row1 = row0 + 8;
            bool v0 = (start + row0 < n);
            bool v1 = (start + row1 < n);
            float* o0 = g_eo + (size_t)(pbase + start + row0) * D;
            float* o1 = g_eo + (size_t)(pbase + start + row1) * D;
            #pragma unroll
            for (int nb = 0; nb < 10; nb++) {
                int col = 8 * nb + bcol;
                float b20 = sb2[col], b21 = sb2[col + 1];
                if (v0) *(float2*)&o0[col] = make_float2(yacc[nb][0] + b20, yacc[nb][1] + b21);
                if (v1) *(float2*)&o1[col] = make_float2(yacc[nb][2] + b20, yacc[nb][3] + b21);
            }
        }
    }
}

// ---------------------------------------------------------------------------
extern "C" void kernel_launch(void* const* d_in, const int* in_sizes, int n_in,
                              void* d_out, int out_size) {
    const float* x  = (const float*)d_in[0];
    const float* Wg = (const float*)d_in[1];
    const float* bg = (const float*)d_in[2];
    const float* W1 = (const float*)d_in[3];
    const float* b1 = (const float*)d_in[4];
    const float* W2 = (const float*)d_in[5];
    const float* b2 = (const float*)d_in[6];
    float* out = (float*)d_out;

    int T = in_sizes[0] / D;

    cudaFuncSetAttribute(ffn_kernel, cudaFuncAttributeMaxDynamicSharedMemorySize, SMEM_TOTAL);

    void *cntp, *bufAp;
    cudaGetSymbolAddress(&cntp,  g_cnt);
    cudaGetSymbolAddress(&bufAp, g_bufA);
    int*   cntb = (int*)cntp;
    float* bufA = (float*)bufAp;

    const int NPREP = 2 * E * NCK * 80 * 64;   // 409600
    prep_kernel<<<(NPREP + 255) / 256, 256>>>(W1, W2);
    zero_kernel<<<1, 64>>>();

    int rb = (T + RTB - 1) / RTB;

    for (int l = 0; l < NL; l++) {
        int mode = (l == 0) ? 2 : 3;
        router_kernel<<<rb, RTB>>>((l == 0) ? x : nullptr,
                                   cntb + (l - 1) * E,
                                   cntb + l * E,
                                   bufA,
                                   Wg + (size_t)l * D * E, bg + l * E,
                                   T, mode);
        ffn_kernel<<<FFNBLK, 256, SMEM_TOTAL>>>((l == 0) ? x : bufA,
                                                cntb + l * E, b1, b2);
    }
    // final combine-only pass -> d_out
    router_kernel<<<rb, RTB>>>(nullptr, cntb + (NL - 1) * E, cntb, out,
                               Wg, bg, T, 1);
}